// round 8
// baseline (speedup 1.0000x reference)
#include <cuda_runtime.h>
#include <cuda_fp16.h>
#include <cstdint>
#include <cstring>

// ---------------- problem constants ----------------
constexpr int Dm    = 768;
constexpr int NE    = 4;
constexpr int Rr    = 32;
constexpr int Bb    = 4;
constexpr int Tt    = 512;
constexpr int NTOK  = Bb * Tt;   // 2048
constexpr int NV    = 50257;
constexpr int NVPAD = 50432;     // 394 * 128

constexpr int BM = 128, BN = 128;
constexpr int NCHUNK = Dm / 64;   // 12 chunks of K=64
constexpr int MBLK = NTOK / BM;   // 16
constexpr int NBLK = NVPAD / BN;  // 394

// ---------------- scratch ----------------
__device__ float  g_x[NTOK * Dm];
__device__ float  g_u[NTOK * NE * Rr];
__device__ float  g_cand[NTOK * Rr];
__device__ int    g_win[NTOK];
// A tiles, fp16 fragment-packed: per (mblk,c): [k16(4)][m16(8)][lane(32)] x uint4
__device__ uint4  g_hp[(size_t)MBLK * NCHUNK * 1024];
// B tiles, fp16 pair-packed: per (nblk,c): [k16(4)][wn(4)][pr(2)][lane(32)] x uint4
__device__ uint4  g_Wp[(size_t)NBLK * NCHUNK * 1024];

// ---------------- helpers ----------------
__device__ __forceinline__ uint32_t h2u(__half a, __half b) {
    __half2 t = __halves2half2(a, b);
    uint32_t u;
    memcpy(&u, &t, 4);
    return u;
}
__device__ __forceinline__ uint32_t smem_u32(const void* p) {
    uint32_t a;
    asm("{ .reg .u64 t; cvta.to.shared.u64 t, %1; cvt.u32.u64 %0, t; }" : "=r"(a) : "l"(p));
    return a;
}
__device__ __forceinline__ void cp16(uint32_t s, const void* g) {
    asm volatile("{ .reg .u64 gg; cvta.to.global.u64 gg, %1; cp.async.cg.shared.global [%0], [gg], 16; }"
                 :: "r"(s), "l"(g));
}
#define CP_COMMIT() asm volatile("cp.async.commit_group;" ::: "memory")
#define CP_WAIT(n)  asm volatile("cp.async.wait_group %0;" :: "n"(n) : "memory")
#define LDS128(r0, r1, r2, r3, a) \
    asm volatile("ld.shared.v4.b32 {%0,%1,%2,%3}, [%4];" \
                 : "=r"(r0), "=r"(r1), "=r"(r2), "=r"(r3) : "r"(a))

// =================================================================
// Kernel A1: embedding gather + routing argmax (1 warp per token)
// =================================================================
__global__ void gather_route_kernel(const int* __restrict__ idx,
                                    const float* __restrict__ W_emb,
                                    const float* __restrict__ G) {
    const int tid  = threadIdx.x;
    const int warp = tid >> 5;
    const int lane = tid & 31;
    const int tok  = blockIdx.x * 8 + warp;
    const int id   = idx[tok];

    const float4* src = (const float4*)(W_emb + (size_t)id * Dm);
    const float4* g4  = (const float4*)G;
    float4* dst = (float4*)(g_x + (size_t)tok * Dm);

    float sc[NE] = {0.f, 0.f, 0.f, 0.f};
#pragma unroll
    for (int t = 0; t < 6; t++) {
        const int i = lane + t * 32;
        float4 v = src[i];
        dst[i] = v;
#pragma unroll
        for (int e = 0; e < NE; e++) {
            float4 gg = g4[e * (Dm / 4) + i];
            sc[e] += v.x * gg.x + v.y * gg.y + v.z * gg.z + v.w * gg.w;
        }
    }
#pragma unroll
    for (int off = 16; off > 0; off >>= 1)
#pragma unroll
        for (int e = 0; e < NE; e++)
            sc[e] += __shfl_down_sync(0xffffffffu, sc[e], off);
    if (lane == 0) {
        int best = 0;
        float bv = sc[0];
#pragma unroll
        for (int e = 1; e < NE; e++)
            if (sc[e] > bv) { bv = sc[e]; best = e; }
        g_win[tok] = best;
    }
}

// =================================================================
// Kernel A2: u = x @ W_in  (tiled SIMT GEMM, W_in staged in smem)
// =================================================================
__global__ void uproj_kernel(const float* __restrict__ W_in) {
    __shared__ float xs[16][64];
    __shared__ float ws[64][128];

    const int tid  = threadIdx.x;
    const int tok0 = blockIdx.x * 16;
    const int tx   = tid & 31;
    const int ty   = tid >> 5;
    const int j0   = tx * 4;
    const int t0   = ty * 2;

    float acc[2][4] = {};

#pragma unroll 1
    for (int ch = 0; ch < 12; ch++) {
        const int d0 = ch * 64;
        {
            const int row = tid >> 4, c4 = tid & 15;
            *(float4*)&xs[row][c4 * 4] =
                *(const float4*)(g_x + (size_t)(tok0 + row) * Dm + d0 + c4 * 4);
        }
        {
            const int d_loc = tid >> 2, e = tid & 3;
            const float4* srcw =
                (const float4*)(W_in + (size_t)e * Dm * Rr + (size_t)(d0 + d_loc) * Rr);
#pragma unroll
            for (int k = 0; k < 8; k++)
                *(float4*)&ws[d_loc][e * 32 + k * 4] = srcw[k];
        }
        __syncthreads();
#pragma unroll 8
        for (int d = 0; d < 64; d++) {
            const float4 w4 = *(const float4*)&ws[d][j0];
            const float x0 = xs[t0][d];
            const float x1 = xs[t0 + 1][d];
            acc[0][0] += x0 * w4.x; acc[0][1] += x0 * w4.y;
            acc[0][2] += x0 * w4.z; acc[0][3] += x0 * w4.w;
            acc[1][0] += x1 * w4.x; acc[1][1] += x1 * w4.y;
            acc[1][2] += x1 * w4.z; acc[1][3] += x1 * w4.w;
        }
        __syncthreads();
    }
#pragma unroll
    for (int tt = 0; tt < 2; tt++)
        *(float4*)&g_u[(size_t)(tok0 + t0 + tt) * (NE * Rr) + j0] =
            make_float4(acc[tt][0], acc[tt][1], acc[tt][2], acc[tt][3]);
}

// =================================================================
// Fused kernel: blocks 0..15  -> one-warp recurrence per (e,b)
//               blocks 16..   -> W_emb fp16 fragment permute
// 512 threads. Recurrence blocks schedule first (long pole) and the
// permute work fills the remaining SMs concurrently.
// =================================================================
__global__ void __launch_bounds__(512)
perm_recur_kernel(const float* __restrict__ W, const float* __restrict__ W_rec) {
    __shared__ int list_s[Tt];
    const int tid = threadIdx.x;

    if (blockIdx.x < 16) {
        // ---------- recurrence block ----------
        if (tid >= 32) return;
        const int e = blockIdx.x >> 2;
        const int b = blockIdx.x & 3;
        const int lane = tid;

        // build winner list for (e,b)
        int n = 0;
        for (int base = 0; base < Tt; base += 32) {
            unsigned m = __ballot_sync(0xffffffffu, g_win[b * Tt + base + lane] == e);
            while (m) {
                int i = __ffs(m) - 1;
                m &= m - 1;
                list_s[n++] = base + i;
            }
        }

        float wcol[Rr];
#pragma unroll
        for (int s = 0; s < Rr; s++) wcol[s] = W_rec[(e * Rr + s) * Rr + lane];

        float st = 0.f;
        float unext = 0.f;
        if (n > 0) unext = g_u[(b * Tt + list_s[0]) * (NE * Rr) + e * Rr + lane];
        for (int i = 0; i < n; i++) {
            const float ucur = unext;
            if (i + 1 < n)
                unext = g_u[(b * Tt + list_s[i + 1]) * (NE * Rr) + e * Rr + lane];
            float a0 = ucur, a1 = 0.f, a2 = 0.f, a3 = 0.f;
#pragma unroll
            for (int s = 0; s < Rr; s += 4) {
                a0 += __shfl_sync(0xffffffffu, st, s)     * wcol[s];
                a1 += __shfl_sync(0xffffffffu, st, s + 1) * wcol[s + 1];
                a2 += __shfl_sync(0xffffffffu, st, s + 2) * wcol[s + 2];
                a3 += __shfl_sync(0xffffffffu, st, s + 3) * wcol[s + 3];
            }
            st = tanhf((a0 + a1) + (a2 + a3));
            g_cand[(b * Tt + list_s[i]) * Rr + lane] = st;
        }
        return;
    }

    // ---------- permute block: 4 chunks x 128 cols ----------
    const int pb   = blockIdx.x - 16;
    const int nblk = pb / 3;
    const int cg   = pb % 3;
    const int c    = cg * 4 + (tid >> 7);
    const int col  = tid & 127;
    const int gcol = nblk * BN + col;

    __half v[64];
    if (gcol < NV) {
        const float4* src = (const float4*)(W + (size_t)gcol * Dm + c * 64);
#pragma unroll
        for (int i = 0; i < 16; i++) {
            float4 q = src[i];
            v[i * 4]     = __float2half_rn(q.x);
            v[i * 4 + 1] = __float2half_rn(q.y);
            v[i * 4 + 2] = __float2half_rn(q.z);
            v[i * 4 + 3] = __float2half_rn(q.w);
        }
    } else {
#pragma unroll
        for (int i = 0; i < 64; i++) v[i] = __float2half_rn(0.f);
    }
    const int wn = col >> 5, pr = (col >> 4) & 1, h = (col >> 3) & 1, g = col & 7;
#pragma unroll
    for (int k16 = 0; k16 < 4; k16++) {
#pragma unroll
        for (int t4 = 0; t4 < 4; t4++) {
            const size_t idx =
                ((((size_t)(nblk * NCHUNK + c) * 4 + k16) * 4 + wn) * 2 + pr) * 32 + g * 4 + t4;
            uint32_t* p = (uint32_t*)(g_Wp + idx);
            p[h * 2]     = h2u(v[k16 * 16 + t4 * 2],     v[k16 * 16 + t4 * 2 + 1]);
            p[h * 2 + 1] = h2u(v[k16 * 16 + 8 + t4 * 2], v[k16 * 16 + 8 + t4 * 2 + 1]);
        }
    }
}

// =================================================================
// Kernel C: y = cand @ W_out[winner] + x, LayerNorm, fp16-round,
//           write DIRECTLY into fragment-packed g_hp.
// =================================================================
__global__ void out_ln_kernel(const float* __restrict__ W_out,
                              const float* __restrict__ gamma,
                              const float* __restrict__ beta) {
    __shared__ float cs[Rr];
    __shared__ float red[2][256];

    const int tok = blockIdx.x;
    const int tid = threadIdx.x;
    const int e   = g_win[tok];

    if (tid < Rr) cs[tid] = g_cand[tok * Rr + tid];
    __syncthreads();

    float y[3];
    float s = 0.f, sq = 0.f;
#pragma unroll
    for (int i = 0; i < 3; i++) {
        const int d = tid + i * 256;
        float acc = g_x[tok * Dm + d];
        const float* wo = W_out + (size_t)e * Rr * Dm + d;
#pragma unroll
        for (int r = 0; r < Rr; r++) acc += cs[r] * wo[(size_t)r * Dm];
        y[i] = acc;
        s += acc;
        sq += acc * acc;
    }
    red[0][tid] = s;
    red[1][tid] = sq;
    __syncthreads();
    for (int off = 128; off > 0; off >>= 1) {
        if (tid < off) {
            red[0][tid] += red[0][tid + off];
            red[1][tid] += red[1][tid + off];
        }
        __syncthreads();
    }
    const float mean = red[0][0] * (1.f / Dm);
    const float var  = red[1][0] * (1.f / Dm) - mean * mean;
    const float rstd = rsqrtf(var + 1e-5f);

    const int mblk    = tok >> 7;
    const int r       = tok & 127;
    const int m16     = r >> 4;
    const int g       = r & 7;
    const int rowhalf = (r >> 3) & 1;
#pragma unroll
    for (int i = 0; i < 3; i++) {
        const int d = tid + i * 256;
        const __half hv = __float2half_rn((y[i] - mean) * rstd * gamma[d] + beta[d]);
        const int c = d >> 6, kk = d & 63;
        const int k16 = kk >> 4, kin = kk & 15;
        const int khalf = kin >> 3, kp = kin & 7;
        const int t4 = kp >> 1, par = kp & 1;
        __half* base = (__half*)(g_hp +
            ((size_t)(mblk * NCHUNK + c) * 4 + k16) * 256 + m16 * 32 + g * 4 + t4);
        base[(khalf * 2 + rowhalf) * 2 + par] = hv;
    }
}

// =================================================================
// Kernel D: logits = h @ W_emb^T, mma.sync m16n8k16 fp16
// CTA 128x128, 8 warps (2 wm x 4 wn), warp tile 64x32.
// A fragments via direct LDG.128 from L2 (double-buffered per k16),
// B via 4-stage cp.async ring (16KB/stage) -> 2 CTAs/SM.
// =================================================================
constexpr int BSTAGE = 16384;              // B-only stage
constexpr int NSTAGE = 4;
constexpr int SM_TOT = NSTAGE * BSTAGE;    // 64KB

__global__ void __launch_bounds__(256, 2)
gemm_tc_kernel(float* __restrict__ out) {
    extern __shared__ char smem[];
    const uint32_t sbase = smem_u32(smem);
    const int tid  = threadIdx.x;
    const int warp = tid >> 5;
    const int lane = tid & 31;
    const int wm   = warp & 1;
    const int wn   = warp >> 1;   // 0..3
    const int g    = lane >> 2;
    const int t4   = lane & 3;
    const int mblk = blockIdx.x;
    const int nblk = blockIdx.y;

    // A fragments: lane-indexed base; frag (kc, mt) at + kc*256 + mt*32
    const uint4* __restrict__ gA =
        g_hp + (size_t)mblk * NCHUNK * 1024 + wm * 128 + lane;
    const uint4* __restrict__ gB = g_Wp + (size_t)nblk * NCHUNK * 1024;

    auto load_stage = [&](int slot, int c) {
        const uint32_t sS = sbase + slot * BSTAGE;
        const uint4* b = gB + c * 1024;
#pragma unroll
        for (int t = 0; t < 4; t++) cp16(sS + (tid + t * 256) * 16, b + tid + t * 256);
        CP_COMMIT();
    };

    load_stage(0, 0);
    load_stage(1, 1);
    load_stage(2, 2);

    uint4 abuf[2][4];
#pragma unroll
    for (int mt = 0; mt < 4; mt++) abuf[0][mt] = gA[mt * 32];   // kc = 0

    float acc[4][4][4];
#pragma unroll
    for (int mt = 0; mt < 4; mt++)
#pragma unroll
        for (int nt = 0; nt < 4; nt++)
#pragma unroll
            for (int k = 0; k < 4; k++) acc[mt][nt][k] = 0.f;

    const uint32_t boff = sbase + wn * 1024 + lane * 16;  // + slot*BSTAGE + k16*4096 + pr*512

#pragma unroll 1
    for (int c = 0; c < NCHUNK; c++) {
        if (c < NCHUNK - 2)       { CP_WAIT(2); }
        else if (c == NCHUNK - 2) { CP_WAIT(1); }
        else                      { CP_WAIT(0); }
        __syncthreads();
        if (c + 3 < NCHUNK) load_stage((c + 3) & 3, c + 3);

        const uint32_t sS = boff + (c & 3) * BSTAGE;
#pragma unroll
        for (int k16 = 0; k16 < 4; k16++) {
            const int kc = c * 4 + k16;
            // prefetch next k16's A fragments into the other buffer
            if (kc + 1 < NCHUNK * 4) {
                const uint4* pa = gA + (kc + 1) * 256;
#pragma unroll
                for (int mt = 0; mt < 4; mt++) abuf[(kc + 1) & 1][mt] = pa[mt * 32];
            }
            uint32_t bf[8];
#pragma unroll
            for (int pr = 0; pr < 2; pr++)
                LDS128(bf[pr * 4], bf[pr * 4 + 1], bf[pr * 4 + 2], bf[pr * 4 + 3],
                       sS + k16 * 4096 + pr * 512);
            const uint4* A = abuf[kc & 1];
#pragma unroll
            for (int mt = 0; mt < 4; mt++)
#pragma unroll
                for (int nt = 0; nt < 4; nt++) {
                    const int bi = (nt >> 1) * 4 + (nt & 1) * 2;
                    asm volatile(
                        "mma.sync.aligned.m16n8k16.row.col.f32.f16.f16.f32 "
                        "{%0,%1,%2,%3}, {%4,%5,%6,%7}, {%8,%9}, {%0,%1,%2,%3};\n"
                        : "+f"(acc[mt][nt][0]), "+f"(acc[mt][nt][1]),
                          "+f"(acc[mt][nt][2]), "+f"(acc[mt][nt][3])
                        : "r"(A[mt].x), "r"(A[mt].y), "r"(A[mt].z), "r"(A[mt].w),
                          "r"(bf[bi]), "r"(bf[bi + 1]));
                }
        }
    }

    const int m0 = mblk * BM;
    const int n0 = nblk * BN;
#pragma unroll
    for (int mt = 0; mt < 4; mt++) {
        const int row0 = m0 + wm * 64 + mt * 16 + g;
#pragma unroll
        for (int nt = 0; nt < 4; nt++) {
            const int col = n0 + wn * 32 + nt * 8 + t4 * 2;
            if (col + 1 < NV) {
                out[(size_t)row0 * NV + col]           = acc[mt][nt][0];
                out[(size_t)row0 * NV + col + 1]       = acc[mt][nt][1];
                out[(size_t)(row0 + 8) * NV + col]     = acc[mt][nt][2];
                out[(size_t)(row0 + 8) * NV + col + 1] = acc[mt][nt][3];
            } else if (col < NV) {
                out[(size_t)row0 * NV + col]       = acc[mt][nt][0];
                out[(size_t)(row0 + 8) * NV + col] = acc[mt][nt][2];
            }
        }
    }
}

// =================================================================
// launch
// =================================================================
extern "C" void kernel_launch(void* const* d_in, const int* in_sizes, int n_in,
                              void* d_out, int out_size) {
    const int*   idx   = (const int*)d_in[0];
    const float* W_emb = (const float*)d_in[1];
    const float* G     = (const float*)d_in[2];
    const float* W_in  = (const float*)d_in[3];
    const float* W_rec = (const float*)d_in[4];
    const float* W_out = (const float*)d_in[5];
    const float* gamma = (const float*)d_in[6];
    const float* beta  = (const float*)d_in[7];
    float* out = (float*)d_out;

    cudaFuncSetAttribute(gemm_tc_kernel,
                         cudaFuncAttributeMaxDynamicSharedMemorySize, SM_TOT);

    gather_route_kernel<<<NTOK / 8, 256>>>(idx, W_emb, G);
    uproj_kernel<<<128, 256>>>(W_in);
    perm_recur_kernel<<<16 + NBLK * 3, 512>>>(W_emb, W_rec);
    out_ln_kernel<<<NTOK, 256>>>(W_out, gamma, beta);

    dim3 grid(MBLK, NBLK);
    gemm_tc_kernel<<<grid, 256, SM_TOT>>>(out);
}

// round 11
// speedup vs baseline: 1.0535x; 1.0535x over previous
#include <cuda_runtime.h>
#include <cuda_fp16.h>
#include <cstdint>
#include <cstring>

// ---------------- problem constants ----------------
constexpr int Dm    = 768;
constexpr int NE    = 4;
constexpr int Rr    = 32;
constexpr int Bb    = 4;
constexpr int Tt    = 512;
constexpr int NTOK  = Bb * Tt;   // 2048
constexpr int NV    = 50257;
constexpr int NVPAD = 50432;     // 394 * 128

constexpr int BM = 128, BN = 128;
constexpr int NCHUNK = Dm / 64;   // 12 chunks of K=64
constexpr int MBLK = NTOK / BM;   // 16
constexpr int NBLK = NVPAD / BN;  // 394

// ---------------- scratch ----------------
__device__ float  g_x[NTOK * Dm];
__device__ float  g_u[NTOK * NE * Rr];
__device__ float  g_cand[NTOK * Rr];
__device__ int    g_win[NTOK];
// A tiles, fp16 fragment-packed: per (mblk,c): [k16(4)][m16(8)][lane(32)] x uint4
__device__ uint4  g_hp[(size_t)MBLK * NCHUNK * 1024];
// B tiles, fp16 pair-packed: per (nblk,c): [k16(4)][wn(4)][pr(2)][lane(32)] x uint4
__device__ uint4  g_Wp[(size_t)NBLK * NCHUNK * 1024];

// ---------------- helpers ----------------
__device__ __forceinline__ uint32_t h2u(__half a, __half b) {
    __half2 t = __halves2half2(a, b);
    uint32_t u;
    memcpy(&u, &t, 4);
    return u;
}
__device__ __forceinline__ uint32_t smem_u32(const void* p) {
    uint32_t a;
    asm("{ .reg .u64 t; cvta.to.shared.u64 t, %1; cvt.u32.u64 %0, t; }" : "=r"(a) : "l"(p));
    return a;
}
__device__ __forceinline__ void cp16(uint32_t s, const void* g) {
    asm volatile("{ .reg .u64 gg; cvta.to.global.u64 gg, %1; cp.async.cg.shared.global [%0], [gg], 16; }"
                 :: "r"(s), "l"(g));
}
#define CP_COMMIT() asm volatile("cp.async.commit_group;" ::: "memory")
#define CP_WAIT(n)  asm volatile("cp.async.wait_group %0;" :: "n"(n) : "memory")
#define LDS128(r0, r1, r2, r3, a) \
    asm volatile("ld.shared.v4.b32 {%0,%1,%2,%3}, [%4];" \
                 : "=r"(r0), "=r"(r1), "=r"(r2), "=r"(r3) : "r"(a))

// =================================================================
// Kernel A1: embedding gather + routing argmax (1 warp per token)
// =================================================================
__global__ void gather_route_kernel(const int* __restrict__ idx,
                                    const float* __restrict__ W_emb,
                                    const float* __restrict__ G) {
    const int tid  = threadIdx.x;
    const int warp = tid >> 5;
    const int lane = tid & 31;
    const int tok  = blockIdx.x * 8 + warp;
    const int id   = idx[tok];

    const float4* src = (const float4*)(W_emb + (size_t)id * Dm);
    const float4* g4  = (const float4*)G;
    float4* dst = (float4*)(g_x + (size_t)tok * Dm);

    float sc[NE] = {0.f, 0.f, 0.f, 0.f};
#pragma unroll
    for (int t = 0; t < 6; t++) {
        const int i = lane + t * 32;
        float4 v = src[i];
        dst[i] = v;
#pragma unroll
        for (int e = 0; e < NE; e++) {
            float4 gg = g4[e * (Dm / 4) + i];
            sc[e] += v.x * gg.x + v.y * gg.y + v.z * gg.z + v.w * gg.w;
        }
    }
#pragma unroll
    for (int off = 16; off > 0; off >>= 1)
#pragma unroll
        for (int e = 0; e < NE; e++)
            sc[e] += __shfl_down_sync(0xffffffffu, sc[e], off);
    if (lane == 0) {
        int best = 0;
        float bv = sc[0];
#pragma unroll
        for (int e = 1; e < NE; e++)
            if (sc[e] > bv) { bv = sc[e]; best = e; }
        g_win[tok] = best;
    }
}

// =================================================================
// Kernel A2: u = x @ W_in  (tiled SIMT GEMM, W_in staged in smem)
// =================================================================
__global__ void uproj_kernel(const float* __restrict__ W_in) {
    __shared__ float xs[16][64];
    __shared__ float ws[64][128];

    const int tid  = threadIdx.x;
    const int tok0 = blockIdx.x * 16;
    const int tx   = tid & 31;
    const int ty   = tid >> 5;
    const int j0   = tx * 4;
    const int t0   = ty * 2;

    float acc[2][4] = {};

#pragma unroll 1
    for (int ch = 0; ch < 12; ch++) {
        const int d0 = ch * 64;
        {
            const int row = tid >> 4, c4 = tid & 15;
            *(float4*)&xs[row][c4 * 4] =
                *(const float4*)(g_x + (size_t)(tok0 + row) * Dm + d0 + c4 * 4);
        }
        {
            const int d_loc = tid >> 2, e = tid & 3;
            const float4* srcw =
                (const float4*)(W_in + (size_t)e * Dm * Rr + (size_t)(d0 + d_loc) * Rr);
#pragma unroll
            for (int k = 0; k < 8; k++)
                *(float4*)&ws[d_loc][e * 32 + k * 4] = srcw[k];
        }
        __syncthreads();
#pragma unroll 8
        for (int d = 0; d < 64; d++) {
            const float4 w4 = *(const float4*)&ws[d][j0];
            const float x0 = xs[t0][d];
            const float x1 = xs[t0 + 1][d];
            acc[0][0] += x0 * w4.x; acc[0][1] += x0 * w4.y;
            acc[0][2] += x0 * w4.z; acc[0][3] += x0 * w4.w;
            acc[1][0] += x1 * w4.x; acc[1][1] += x1 * w4.y;
            acc[1][2] += x1 * w4.z; acc[1][3] += x1 * w4.w;
        }
        __syncthreads();
    }
#pragma unroll
    for (int tt = 0; tt < 2; tt++)
        *(float4*)&g_u[(size_t)(tok0 + t0 + tt) * (NE * Rr) + j0] =
            make_float4(acc[tt][0], acc[tt][1], acc[tt][2], acc[tt][3]);
}

// =================================================================
// Fused kernel: blocks 0..15  -> one-warp recurrence per (e,b)
//               blocks 16..   -> W_emb fp16 fragment permute
// =================================================================
__global__ void __launch_bounds__(512)
perm_recur_kernel(const float* __restrict__ W, const float* __restrict__ W_rec) {
    __shared__ int list_s[Tt];
    const int tid = threadIdx.x;

    if (blockIdx.x < 16) {
        if (tid >= 32) return;
        const int e = blockIdx.x >> 2;
        const int b = blockIdx.x & 3;
        const int lane = tid;

        int n = 0;
        for (int base = 0; base < Tt; base += 32) {
            unsigned m = __ballot_sync(0xffffffffu, g_win[b * Tt + base + lane] == e);
            while (m) {
                int i = __ffs(m) - 1;
                m &= m - 1;
                list_s[n++] = base + i;
            }
        }

        float wcol[Rr];
#pragma unroll
        for (int s = 0; s < Rr; s++) wcol[s] = W_rec[(e * Rr + s) * Rr + lane];

        float st = 0.f;
        float unext = 0.f;
        if (n > 0) unext = g_u[(b * Tt + list_s[0]) * (NE * Rr) + e * Rr + lane];
        for (int i = 0; i < n; i++) {
            const float ucur = unext;
            if (i + 1 < n)
                unext = g_u[(b * Tt + list_s[i + 1]) * (NE * Rr) + e * Rr + lane];
            float a0 = ucur, a1 = 0.f, a2 = 0.f, a3 = 0.f;
#pragma unroll
            for (int s = 0; s < Rr; s += 4) {
                a0 += __shfl_sync(0xffffffffu, st, s)     * wcol[s];
                a1 += __shfl_sync(0xffffffffu, st, s + 1) * wcol[s + 1];
                a2 += __shfl_sync(0xffffffffu, st, s + 2) * wcol[s + 2];
                a3 += __shfl_sync(0xffffffffu, st, s + 3) * wcol[s + 3];
            }
            st = tanhf((a0 + a1) + (a2 + a3));
            g_cand[(b * Tt + list_s[i]) * Rr + lane] = st;
        }
        return;
    }

    // ---------- permute block: 4 chunks x 128 cols ----------
    const int pb   = blockIdx.x - 16;
    const int nblk = pb / 3;
    const int cg   = pb % 3;
    const int c    = cg * 4 + (tid >> 7);
    const int col  = tid & 127;
    const int gcol = nblk * BN + col;

    __half v[64];
    if (gcol < NV) {
        const float4* src = (const float4*)(W + (size_t)gcol * Dm + c * 64);
#pragma unroll
        for (int i = 0; i < 16; i++) {
            float4 q = src[i];
            v[i * 4]     = __float2half_rn(q.x);
            v[i * 4 + 1] = __float2half_rn(q.y);
            v[i * 4 + 2] = __float2half_rn(q.z);
            v[i * 4 + 3] = __float2half_rn(q.w);
        }
    } else {
#pragma unroll
        for (int i = 0; i < 64; i++) v[i] = __float2half_rn(0.f);
    }
    const int wn = col >> 5, pr = (col >> 4) & 1, h = (col >> 3) & 1, g = col & 7;
#pragma unroll
    for (int k16 = 0; k16 < 4; k16++) {
#pragma unroll
        for (int t4 = 0; t4 < 4; t4++) {
            const size_t idx =
                ((((size_t)(nblk * NCHUNK + c) * 4 + k16) * 4 + wn) * 2 + pr) * 32 + g * 4 + t4;
            uint32_t* p = (uint32_t*)(g_Wp + idx);
            p[h * 2]     = h2u(v[k16 * 16 + t4 * 2],     v[k16 * 16 + t4 * 2 + 1]);
            p[h * 2 + 1] = h2u(v[k16 * 16 + 8 + t4 * 2], v[k16 * 16 + 8 + t4 * 2 + 1]);
        }
    }
}

// =================================================================
// Kernel C: y = cand @ W_out[winner] + x, LayerNorm, fp16-round,
//           write DIRECTLY into fragment-packed g_hp.
// =================================================================
__global__ void out_ln_kernel(const float* __restrict__ W_out,
                              const float* __restrict__ gamma,
                              const float* __restrict__ beta) {
    __shared__ float cs[Rr];
    __shared__ float red[2][256];

    const int tok = blockIdx.x;
    const int tid = threadIdx.x;
    const int e   = g_win[tok];

    if (tid < Rr) cs[tid] = g_cand[tok * Rr + tid];
    __syncthreads();

    float y[3];
    float s = 0.f, sq = 0.f;
#pragma unroll
    for (int i = 0; i < 3; i++) {
        const int d = tid + i * 256;
        float acc = g_x[tok * Dm + d];
        const float* wo = W_out + (size_t)e * Rr * Dm + d;
#pragma unroll
        for (int r = 0; r < Rr; r++) acc += cs[r] * wo[(size_t)r * Dm];
        y[i] = acc;
        s += acc;
        sq += acc * acc;
    }
    red[0][tid] = s;
    red[1][tid] = sq;
    __syncthreads();
    for (int off = 128; off > 0; off >>= 1) {
        if (tid < off) {
            red[0][tid] += red[0][tid + off];
            red[1][tid] += red[1][tid + off];
        }
        __syncthreads();
    }
    const float mean = red[0][0] * (1.f / Dm);
    const float var  = red[1][0] * (1.f / Dm) - mean * mean;
    const float rstd = rsqrtf(var + 1e-5f);

    const int mblk    = tok >> 7;
    const int r       = tok & 127;
    const int m16     = r >> 4;
    const int g       = r & 7;
    const int rowhalf = (r >> 3) & 1;
#pragma unroll
    for (int i = 0; i < 3; i++) {
        const int d = tid + i * 256;
        const __half hv = __float2half_rn((y[i] - mean) * rstd * gamma[d] + beta[d]);
        const int c = d >> 6, kk = d & 63;
        const int k16 = kk >> 4, kin = kk & 15;
        const int khalf = kin >> 3, kp = kin & 7;
        const int t4 = kp >> 1, par = kp & 1;
        __half* base = (__half*)(g_hp +
            ((size_t)(mblk * NCHUNK + c) * 4 + k16) * 256 + m16 * 32 + g * 4 + t4);
        base[(khalf * 2 + rowhalf) * 2 + par] = hv;
    }
}

// =================================================================
// Kernel D (round-7 form): logits = h @ W_emb^T, mma.sync m16n8k16
// CTA 128x128, 8 warps (2 wm x 4 wn), warp tile 64x32.
// A+B smem, 3-stage ring (96KB) -> 2 CTAs/SM.
// =================================================================
constexpr int STAGE_BYTES = 32768;            // 16KB A + 16KB B
constexpr int SM_TOT      = 3 * STAGE_BYTES;  // 96KB

__global__ void __launch_bounds__(256, 2)
gemm_tc_kernel(float* __restrict__ out) {
    extern __shared__ char smem[];
    const uint32_t sbase = smem_u32(smem);
    const int tid  = threadIdx.x;
    const int warp = tid >> 5;
    const int lane = tid & 31;
    const int wm   = warp & 1;
    const int wn   = warp >> 1;   // 0..3
    const int g    = lane >> 2;
    const int t4   = lane & 3;
    const int mblk = blockIdx.x;
    const int nblk = blockIdx.y;

    const uint4* gA = g_hp + (size_t)mblk * NCHUNK * 1024;
    const uint4* gB = g_Wp + (size_t)nblk * NCHUNK * 1024;

    auto load_stage = [&](int slot, int c) {
        const uint32_t sS = sbase + slot * STAGE_BYTES;
        const uint4* a = gA + c * 1024;
        const uint4* b = gB + c * 1024;
#pragma unroll
        for (int t = 0; t < 4; t++) cp16(sS + (tid + t * 256) * 16, a + tid + t * 256);
#pragma unroll
        for (int t = 0; t < 4; t++) cp16(sS + 16384 + (tid + t * 256) * 16, b + tid + t * 256);
        CP_COMMIT();
    };

    load_stage(0, 0);
    load_stage(1, 1);

    float acc[4][4][4];
#pragma unroll
    for (int mt = 0; mt < 4; mt++)
#pragma unroll
        for (int nt = 0; nt < 4; nt++)
#pragma unroll
            for (int k = 0; k < 4; k++) acc[mt][nt][k] = 0.f;

    const uint32_t aoff = (wm * 4) * 512 + lane * 16;            // + k16*4096 + mt*512
    const uint32_t boff = 16384 + wn * 1024 + lane * 16;         // + k16*4096 + pr*512

#pragma unroll 1
    for (int c = 0; c < NCHUNK; c++) {
        if (c < NCHUNK - 1) { CP_WAIT(1); } else { CP_WAIT(0); }
        __syncthreads();
        if (c + 2 < NCHUNK) load_stage((c + 2) % 3, c + 2);

        const uint32_t sS = sbase + (c % 3) * STAGE_BYTES;
#pragma unroll
        for (int k16 = 0; k16 < 4; k16++) {
            uint32_t af[16], bf[8];
#pragma unroll
            for (int mt = 0; mt < 4; mt++)
                LDS128(af[mt * 4], af[mt * 4 + 1], af[mt * 4 + 2], af[mt * 4 + 3],
                       sS + aoff + k16 * 4096 + mt * 512);
#pragma unroll
            for (int pr = 0; pr < 2; pr++)
                LDS128(bf[pr * 4], bf[pr * 4 + 1], bf[pr * 4 + 2], bf[pr * 4 + 3],
                       sS + boff + k16 * 4096 + pr * 512);
#pragma unroll
            for (int mt = 0; mt < 4; mt++)
#pragma unroll
                for (int nt = 0; nt < 4; nt++) {
                    const int bi = (nt >> 1) * 4 + (nt & 1) * 2;
                    asm volatile(
                        "mma.sync.aligned.m16n8k16.row.col.f32.f16.f16.f32 "
                        "{%0,%1,%2,%3}, {%4,%5,%6,%7}, {%8,%9}, {%0,%1,%2,%3};\n"
                        : "+f"(acc[mt][nt][0]), "+f"(acc[mt][nt][1]),
                          "+f"(acc[mt][nt][2]), "+f"(acc[mt][nt][3])
                        : "r"(af[mt * 4]), "r"(af[mt * 4 + 1]),
                          "r"(af[mt * 4 + 2]), "r"(af[mt * 4 + 3]),
                          "r"(bf[bi]), "r"(bf[bi + 1]));
                }
        }
    }

    const int m0 = mblk * BM;
    const int n0 = nblk * BN;
#pragma unroll
    for (int mt = 0; mt < 4; mt++) {
        const int row0 = m0 + wm * 64 + mt * 16 + g;
#pragma unroll
        for (int nt = 0; nt < 4; nt++) {
            const int col = n0 + wn * 32 + nt * 8 + t4 * 2;
            if (col + 1 < NV) {
                out[(size_t)row0 * NV + col]           = acc[mt][nt][0];
                out[(size_t)row0 * NV + col + 1]       = acc[mt][nt][1];
                out[(size_t)(row0 + 8) * NV + col]     = acc[mt][nt][2];
                out[(size_t)(row0 + 8) * NV + col + 1] = acc[mt][nt][3];
            } else if (col < NV) {
                out[(size_t)row0 * NV + col]       = acc[mt][nt][0];
                out[(size_t)(row0 + 8) * NV + col] = acc[mt][nt][2];
            }
        }
    }
}

// =================================================================
// launch
// =================================================================
extern "C" void kernel_launch(void* const* d_in, const int* in_sizes, int n_in,
                              void* d_out, int out_size) {
    const int*   idx   = (const int*)d_in[0];
    const float* W_emb = (const float*)d_in[1];
    const float* G     = (const float*)d_in[2];
    const float* W_in  = (const float*)d_in[3];
    const float* W_rec = (const float*)d_in[4];
    const float* W_out = (const float*)d_in[5];
    const float* gamma = (const float*)d_in[6];
    const float* beta  = (const float*)d_in[7];
    float* out = (float*)d_out;

    cudaFuncSetAttribute(gemm_tc_kernel,
                         cudaFuncAttributeMaxDynamicSharedMemorySize, SM_TOT);

    gather_route_kernel<<<NTOK / 8, 256>>>(idx, W_emb, G);
    uproj_kernel<<<128, 256>>>(W_in);
    perm_recur_kernel<<<16 + NBLK * 3, 512>>>(W_emb, W_rec);
    out_ln_kernel<<<NTOK, 256>>>(W_out, gamma, beta);

    dim3 grid(MBLK, NBLK);
    gemm_tc_kernel<<<grid, 256, SM_TOT>>>(out);
}

// round 13
// speedup vs baseline: 1.1544x; 1.0957x over previous
#include <cuda_runtime.h>
#include <cuda_fp16.h>
#include <cstdint>
#include <cstring>

// ---------------- problem constants ----------------
constexpr int Dm    = 768;
constexpr int NE    = 4;
constexpr int Rr    = 32;
constexpr int Bb    = 4;
constexpr int Tt    = 512;
constexpr int NTOK  = Bb * Tt;   // 2048
constexpr int NV    = 50257;
constexpr int NVPAD = 50432;     // 394 * 128

constexpr int BM = 128, BN = 128;
constexpr int NCHUNK = Dm / 64;   // 12 chunks of K=64
constexpr int MBLK = NTOK / BM;   // 16
constexpr int NBLK = NVPAD / BN;  // 394

// ---------------- scratch ----------------
__device__ float  g_x[NTOK * Dm];
__device__ float  g_u[NTOK * NE * Rr];
__device__ float  g_cand[NTOK * Rr];
__device__ int    g_win[NTOK];
// A tiles, fp16 fragment-packed: per (mblk,c): [k16(4)][m16(8)][lane(32)] x uint4
__device__ uint4  g_hp[(size_t)MBLK * NCHUNK * 1024];
// B tiles, fp16 pair-packed: per (nblk,c): [k16(4)][wn(4)][pr(2)][lane(32)] x uint4
__device__ uint4  g_Wp[(size_t)NBLK * NCHUNK * 1024];

// ---------------- helpers ----------------
__device__ __forceinline__ uint32_t h2u(__half a, __half b) {
    __half2 t = __halves2half2(a, b);
    uint32_t u;
    memcpy(&u, &t, 4);
    return u;
}
__device__ __forceinline__ uint32_t smem_u32(const void* p) {
    uint32_t a;
    asm("{ .reg .u64 t; cvta.to.shared.u64 t, %1; cvt.u32.u64 %0, t; }" : "=r"(a) : "l"(p));
    return a;
}
__device__ __forceinline__ void cp16(uint32_t s, const void* g) {
    asm volatile("{ .reg .u64 gg; cvta.to.global.u64 gg, %1; cp.async.cg.shared.global [%0], [gg], 16; }"
                 :: "r"(s), "l"(g));
}
#define CP_COMMIT() asm volatile("cp.async.commit_group;" ::: "memory")
#define CP_WAIT(n)  asm volatile("cp.async.wait_group %0;" :: "n"(n) : "memory")
#define LDS128(r0, r1, r2, r3, a) \
    asm volatile("ld.shared.v4.b32 {%0,%1,%2,%3}, [%4];" \
                 : "=r"(r0), "=r"(r1), "=r"(r2), "=r"(r3) : "r"(a))

// fast tanh: 1 - 2/(e^{2x}+1); MUFU-based, exact at +-inf, rel err ~1e-6
__device__ __forceinline__ float fast_tanh(float x) {
    float e = __expf(2.f * x);
    return 1.f - __fdividef(2.f, e + 1.f);
}

// =================================================================
// Kernel A1: embedding gather + routing argmax (1 warp per token)
// =================================================================
__global__ void gather_route_kernel(const int* __restrict__ idx,
                                    const float* __restrict__ W_emb,
                                    const float* __restrict__ G) {
    const int tid  = threadIdx.x;
    const int warp = tid >> 5;
    const int lane = tid & 31;
    const int tok  = blockIdx.x * 8 + warp;
    const int id   = idx[tok];

    const float4* src = (const float4*)(W_emb + (size_t)id * Dm);
    const float4* g4  = (const float4*)G;
    float4* dst = (float4*)(g_x + (size_t)tok * Dm);

    float sc[NE] = {0.f, 0.f, 0.f, 0.f};
#pragma unroll
    for (int t = 0; t < 6; t++) {
        const int i = lane + t * 32;
        float4 v = src[i];
        dst[i] = v;
#pragma unroll
        for (int e = 0; e < NE; e++) {
            float4 gg = g4[e * (Dm / 4) + i];
            sc[e] += v.x * gg.x + v.y * gg.y + v.z * gg.z + v.w * gg.w;
        }
    }
#pragma unroll
    for (int off = 16; off > 0; off >>= 1)
#pragma unroll
        for (int e = 0; e < NE; e++)
            sc[e] += __shfl_down_sync(0xffffffffu, sc[e], off);
    if (lane == 0) {
        int best = 0;
        float bv = sc[0];
#pragma unroll
        for (int e = 1; e < NE; e++)
            if (sc[e] > bv) { bv = sc[e]; best = e; }
        g_win[tok] = best;
    }
}

// =================================================================
// Kernel A2: u = x @ W_in  (tiled SIMT GEMM, W_in staged in smem)
// =================================================================
__global__ void uproj_kernel(const float* __restrict__ W_in) {
    __shared__ float xs[16][64];
    __shared__ float ws[64][128];

    const int tid  = threadIdx.x;
    const int tok0 = blockIdx.x * 16;
    const int tx   = tid & 31;
    const int ty   = tid >> 5;
    const int j0   = tx * 4;
    const int t0   = ty * 2;

    float acc[2][4] = {};

#pragma unroll 1
    for (int ch = 0; ch < 12; ch++) {
        const int d0 = ch * 64;
        {
            const int row = tid >> 4, c4 = tid & 15;
            *(float4*)&xs[row][c4 * 4] =
                *(const float4*)(g_x + (size_t)(tok0 + row) * Dm + d0 + c4 * 4);
        }
        {
            const int d_loc = tid >> 2, e = tid & 3;
            const float4* srcw =
                (const float4*)(W_in + (size_t)e * Dm * Rr + (size_t)(d0 + d_loc) * Rr);
#pragma unroll
            for (int k = 0; k < 8; k++)
                *(float4*)&ws[d_loc][e * 32 + k * 4] = srcw[k];
        }
        __syncthreads();
#pragma unroll 8
        for (int d = 0; d < 64; d++) {
            const float4 w4 = *(const float4*)&ws[d][j0];
            const float x0 = xs[t0][d];
            const float x1 = xs[t0 + 1][d];
            acc[0][0] += x0 * w4.x; acc[0][1] += x0 * w4.y;
            acc[0][2] += x0 * w4.z; acc[0][3] += x0 * w4.w;
            acc[1][0] += x1 * w4.x; acc[1][1] += x1 * w4.y;
            acc[1][2] += x1 * w4.z; acc[1][3] += x1 * w4.w;
        }
        __syncthreads();
    }
#pragma unroll
    for (int tt = 0; tt < 2; tt++)
        *(float4*)&g_u[(size_t)(tok0 + t0 + tt) * (NE * Rr) + j0] =
            make_float4(acc[tt][0], acc[tt][1], acc[tt][2], acc[tt][3]);
}

// =================================================================
// Kernel B: recurrence, 16 blocks x 1 warp (one (e,b) chain per SM)
// =================================================================
__global__ void __launch_bounds__(32)
recur_kernel(const float* __restrict__ W_rec) {
    __shared__ int list_s[Tt];
    const int lane = threadIdx.x;
    const int e = blockIdx.x >> 2;
    const int b = blockIdx.x & 3;

    // build this (e,b) winner list
    int n = 0;
    for (int base = 0; base < Tt; base += 32) {
        unsigned m = __ballot_sync(0xffffffffu, g_win[b * Tt + base + lane] == e);
        while (m) {
            int i = __ffs(m) - 1;
            m &= m - 1;
            list_s[n++] = base + i;
        }
    }

    float wcol[Rr];
#pragma unroll
    for (int s = 0; s < Rr; s++) wcol[s] = W_rec[(e * Rr + s) * Rr + lane];

    float st = 0.f;
    float unext = 0.f;
    if (n > 0) unext = g_u[(b * Tt + list_s[0]) * (NE * Rr) + e * Rr + lane];
    for (int i = 0; i < n; i++) {
        const float ucur = unext;
        if (i + 1 < n)
            unext = g_u[(b * Tt + list_s[i + 1]) * (NE * Rr) + e * Rr + lane];
        float a0 = ucur, a1 = 0.f, a2 = 0.f, a3 = 0.f;
#pragma unroll
        for (int s = 0; s < Rr; s += 4) {
            a0 += __shfl_sync(0xffffffffu, st, s)     * wcol[s];
            a1 += __shfl_sync(0xffffffffu, st, s + 1) * wcol[s + 1];
            a2 += __shfl_sync(0xffffffffu, st, s + 2) * wcol[s + 2];
            a3 += __shfl_sync(0xffffffffu, st, s + 3) * wcol[s + 3];
        }
        st = fast_tanh((a0 + a1) + (a2 + a3));
        g_cand[(b * Tt + list_s[i]) * Rr + lane] = st;
    }
}

// =================================================================
// Kernel W: W_emb -> fp16, fragment-packed g_Wp (standalone, runs alone)
// =================================================================
__global__ void perm_wemb_kernel(const float* __restrict__ W) {
    const int c    = blockIdx.x;
    const int nblk = blockIdx.y;
    const int col  = threadIdx.x;
    const int gcol = nblk * BN + col;

    __half v[64];
    if (gcol < NV) {
        const float4* src = (const float4*)(W + (size_t)gcol * Dm + c * 64);
#pragma unroll
        for (int i = 0; i < 16; i++) {
            float4 q = src[i];
            v[i * 4]     = __float2half_rn(q.x);
            v[i * 4 + 1] = __float2half_rn(q.y);
            v[i * 4 + 2] = __float2half_rn(q.z);
            v[i * 4 + 3] = __float2half_rn(q.w);
        }
    } else {
#pragma unroll
        for (int i = 0; i < 64; i++) v[i] = __float2half_rn(0.f);
    }
    const int wn = col >> 5, pr = (col >> 4) & 1, h = (col >> 3) & 1, g = col & 7;
#pragma unroll
    for (int k16 = 0; k16 < 4; k16++) {
#pragma unroll
        for (int t4 = 0; t4 < 4; t4++) {
            const size_t idx =
                ((((size_t)(nblk * NCHUNK + c) * 4 + k16) * 4 + wn) * 2 + pr) * 32 + g * 4 + t4;
            uint32_t* p = (uint32_t*)(g_Wp + idx);
            p[h * 2]     = h2u(v[k16 * 16 + t4 * 2],     v[k16 * 16 + t4 * 2 + 1]);
            p[h * 2 + 1] = h2u(v[k16 * 16 + 8 + t4 * 2], v[k16 * 16 + 8 + t4 * 2 + 1]);
        }
    }
}

// =================================================================
// Kernel C: y = cand @ W_out[winner] + x, LayerNorm, fp16-round,
//           write DIRECTLY into fragment-packed g_hp.
// =================================================================
__global__ void out_ln_kernel(const float* __restrict__ W_out,
                              const float* __restrict__ gamma,
                              const float* __restrict__ beta) {
    __shared__ float cs[Rr];
    __shared__ float red[2][256];

    const int tok = blockIdx.x;
    const int tid = threadIdx.x;
    const int e   = g_win[tok];

    if (tid < Rr) cs[tid] = g_cand[tok * Rr + tid];
    __syncthreads();

    float y[3];
    float s = 0.f, sq = 0.f;
#pragma unroll
    for (int i = 0; i < 3; i++) {
        const int d = tid + i * 256;
        float acc = g_x[tok * Dm + d];
        const float* wo = W_out + (size_t)e * Rr * Dm + d;
#pragma unroll
        for (int r = 0; r < Rr; r++) acc += cs[r] * wo[(size_t)r * Dm];
        y[i] = acc;
        s += acc;
        sq += acc * acc;
    }
    red[0][tid] = s;
    red[1][tid] = sq;
    __syncthreads();
    for (int off = 128; off > 0; off >>= 1) {
        if (tid < off) {
            red[0][tid] += red[0][tid + off];
            red[1][tid] += red[1][tid + off];
        }
        __syncthreads();
    }
    const float mean = red[0][0] * (1.f / Dm);
    const float var  = red[1][0] * (1.f / Dm) - mean * mean;
    const float rstd = rsqrtf(var + 1e-5f);

    const int mblk    = tok >> 7;
    const int r       = tok & 127;
    const int m16     = r >> 4;
    const int g       = r & 7;
    const int rowhalf = (r >> 3) & 1;
#pragma unroll
    for (int i = 0; i < 3; i++) {
        const int d = tid + i * 256;
        const __half hv = __float2half_rn((y[i] - mean) * rstd * gamma[d] + beta[d]);
        const int c = d >> 6, kk = d & 63;
        const int k16 = kk >> 4, kin = kk & 15;
        const int khalf = kin >> 3, kp = kin & 7;
        const int t4 = kp >> 1, par = kp & 1;
        __half* base = (__half*)(g_hp +
            ((size_t)(mblk * NCHUNK + c) * 4 + k16) * 256 + m16 * 32 + g * 4 + t4);
        base[(khalf * 2 + rowhalf) * 2 + par] = hv;
    }
}

// =================================================================
// Kernel D (round-7 form, measured 492us): logits = h @ W_emb^T
// CTA 128x128, 8 warps (2 wm x 4 wn), warp tile 64x32.
// A+B smem, 3-stage ring (96KB) -> 2 CTAs/SM.
// =================================================================
constexpr int STAGE_BYTES = 32768;            // 16KB A + 16KB B
constexpr int SM_TOT      = 3 * STAGE_BYTES;  // 96KB

__global__ void __launch_bounds__(256, 2)
gemm_tc_kernel(float* __restrict__ out) {
    extern __shared__ char smem[];
    const uint32_t sbase = smem_u32(smem);
    const int tid  = threadIdx.x;
    const int warp = tid >> 5;
    const int lane = tid & 31;
    const int wm   = warp & 1;
    const int wn   = warp >> 1;   // 0..3
    const int g    = lane >> 2;
    const int t4   = lane & 3;
    const int mblk = blockIdx.x;
    const int nblk = blockIdx.y;

    const uint4* gA = g_hp + (size_t)mblk * NCHUNK * 1024;
    const uint4* gB = g_Wp + (size_t)nblk * NCHUNK * 1024;

    auto load_stage = [&](int slot, int c) {
        const uint32_t sS = sbase + slot * STAGE_BYTES;
        const uint4* a = gA + c * 1024;
        const uint4* b = gB + c * 1024;
#pragma unroll
        for (int t = 0; t < 4; t++) cp16(sS + (tid + t * 256) * 16, a + tid + t * 256);
#pragma unroll
        for (int t = 0; t < 4; t++) cp16(sS + 16384 + (tid + t * 256) * 16, b + tid + t * 256);
        CP_COMMIT();
    };

    load_stage(0, 0);
    load_stage(1, 1);

    float acc[4][4][4];
#pragma unroll
    for (int mt = 0; mt < 4; mt++)
#pragma unroll
        for (int nt = 0; nt < 4; nt++)
#pragma unroll
            for (int k = 0; k < 4; k++) acc[mt][nt][k] = 0.f;

    const uint32_t aoff = (wm * 4) * 512 + lane * 16;            // + k16*4096 + mt*512
    const uint32_t boff = 16384 + wn * 1024 + lane * 16;         // + k16*4096 + pr*512

#pragma unroll 1
    for (int c = 0; c < NCHUNK; c++) {
        if (c < NCHUNK - 1) { CP_WAIT(1); } else { CP_WAIT(0); }
        __syncthreads();
        if (c + 2 < NCHUNK) load_stage((c + 2) % 3, c + 2);

        const uint32_t sS = sbase + (c % 3) * STAGE_BYTES;
#pragma unroll
        for (int k16 = 0; k16 < 4; k16++) {
            uint32_t af[16], bf[8];
#pragma unroll
            for (int mt = 0; mt < 4; mt++)
                LDS128(af[mt * 4], af[mt * 4 + 1], af[mt * 4 + 2], af[mt * 4 + 3],
                       sS + aoff + k16 * 4096 + mt * 512);
#pragma unroll
            for (int pr = 0; pr < 2; pr++)
                LDS128(bf[pr * 4], bf[pr * 4 + 1], bf[pr * 4 + 2], bf[pr * 4 + 3],
                       sS + boff + k16 * 4096 + pr * 512);
#pragma unroll
            for (int mt = 0; mt < 4; mt++)
#pragma unroll
                for (int nt = 0; nt < 4; nt++) {
                    const int bi = (nt >> 1) * 4 + (nt & 1) * 2;
                    asm volatile(
                        "mma.sync.aligned.m16n8k16.row.col.f32.f16.f16.f32 "
                        "{%0,%1,%2,%3}, {%4,%5,%6,%7}, {%8,%9}, {%0,%1,%2,%3};\n"
                        : "+f"(acc[mt][nt][0]), "+f"(acc[mt][nt][1]),
                          "+f"(acc[mt][nt][2]), "+f"(acc[mt][nt][3])
                        : "r"(af[mt * 4]), "r"(af[mt * 4 + 1]),
                          "r"(af[mt * 4 + 2]), "r"(af[mt * 4 + 3]),
                          "r"(bf[bi]), "r"(bf[bi + 1]));
                }
        }
    }

    const int m0 = mblk * BM;
    const int n0 = nblk * BN;
#pragma unroll
    for (int mt = 0; mt < 4; mt++) {
        const int row0 = m0 + wm * 64 + mt * 16 + g;
#pragma unroll
        for (int nt = 0; nt < 4; nt++) {
            const int col = n0 + wn * 32 + nt * 8 + t4 * 2;
            if (col + 1 < NV) {
                out[(size_t)row0 * NV + col]           = acc[mt][nt][0];
                out[(size_t)row0 * NV + col + 1]       = acc[mt][nt][1];
                out[(size_t)(row0 + 8) * NV + col]     = acc[mt][nt][2];
                out[(size_t)(row0 + 8) * NV + col + 1] = acc[mt][nt][3];
            } else if (col < NV) {
                out[(size_t)row0 * NV + col]       = acc[mt][nt][0];
                out[(size_t)(row0 + 8) * NV + col] = acc[mt][nt][2];
            }
        }
    }
}

// =================================================================
// launch
// =================================================================
extern "C" void kernel_launch(void* const* d_in, const int* in_sizes, int n_in,
                              void* d_out, int out_size) {
    const int*   idx   = (const int*)d_in[0];
    const float* W_emb = (const float*)d_in[1];
    const float* G     = (const float*)d_in[2];
    const float* W_in  = (const float*)d_in[3];
    const float* W_rec = (const float*)d_in[4];
    const float* W_out = (const float*)d_in[5];
    const float* gamma = (const float*)d_in[6];
    const float* beta  = (const float*)d_in[7];
    float* out = (float*)d_out;

    cudaFuncSetAttribute(gemm_tc_kernel,
                         cudaFuncAttributeMaxDynamicSharedMemorySize, SM_TOT);

    gather_route_kernel<<<NTOK / 8, 256>>>(idx, W_emb, G);
    uproj_kernel<<<128, 256>>>(W_in);
    recur_kernel<<<16, 32>>>(W_rec);            // runs alone: latency-critical
    perm_wemb_kernel<<<dim3(NCHUNK, NBLK), 128>>>(W_emb);  // runs alone: bandwidth hog
    out_ln_kernel<<<NTOK, 256>>>(W_out, gamma, beta);

    dim3 grid(MBLK, NBLK);
    gemm_tc_kernel<<<grid, 256, SM_TOT>>>(out);
}

// round 14
// speedup vs baseline: 1.1676x; 1.0115x over previous
#include <cuda_runtime.h>
#include <cuda_fp16.h>
#include <cstdint>
#include <cstring>

// ---------------- problem constants ----------------
constexpr int Dm    = 768;
constexpr int NE    = 4;
constexpr int Rr    = 32;
constexpr int Bb    = 4;
constexpr int Tt    = 512;
constexpr int NTOK  = Bb * Tt;   // 2048
constexpr int NV    = 50257;
constexpr int NVPAD = 50432;     // 394 * 128

constexpr int BM = 128, BN = 128;
constexpr int NCHUNK = Dm / 64;   // 12 chunks of K=64
constexpr int MBLK = NTOK / BM;   // 16
constexpr int NBLK = NVPAD / BN;  // 394

// ---------------- scratch ----------------
__device__ float  g_x[NTOK * Dm];
__device__ float  g_u[NTOK * NE * Rr];
__device__ float  g_cand[NTOK * Rr];
__device__ int    g_win[NTOK];
// A tiles, fp16 fragment-packed: per (mblk,c): [k16(4)][m16(8)][lane(32)] x uint4
__device__ uint4  g_hp[(size_t)MBLK * NCHUNK * 1024];
// B tiles, fp16 pair-packed: per (nblk,c): [k16(4)][wn(4)][pr(2)][lane(32)] x uint4
__device__ uint4  g_Wp[(size_t)NBLK * NCHUNK * 1024];

// ---------------- helpers ----------------
__device__ __forceinline__ uint32_t h2u(__half a, __half b) {
    __half2 t = __halves2half2(a, b);
    uint32_t u;
    memcpy(&u, &t, 4);
    return u;
}
__device__ __forceinline__ uint32_t smem_u32(const void* p) {
    uint32_t a;
    asm("{ .reg .u64 t; cvta.to.shared.u64 t, %1; cvt.u32.u64 %0, t; }" : "=r"(a) : "l"(p));
    return a;
}
__device__ __forceinline__ void cp16(uint32_t s, const void* g) {
    asm volatile("{ .reg .u64 gg; cvta.to.global.u64 gg, %1; cp.async.cg.shared.global [%0], [gg], 16; }"
                 :: "r"(s), "l"(g));
}
#define CP_COMMIT() asm volatile("cp.async.commit_group;" ::: "memory")
#define CP_WAIT(n)  asm volatile("cp.async.wait_group %0;" :: "n"(n) : "memory")
#define LDS128(r0, r1, r2, r3, a) \
    asm volatile("ld.shared.v4.b32 {%0,%1,%2,%3}, [%4];" \
                 : "=r"(r0), "=r"(r1), "=r"(r2), "=r"(r3) : "r"(a))

// fast tanh: 1 - 2/(e^{2x}+1); MUFU-based, exact at +-inf, rel err ~1e-6
__device__ __forceinline__ float fast_tanh(float x) {
    float e = __expf(2.f * x);
    return 1.f - __fdividef(2.f, e + 1.f);
}

// =================================================================
// Kernel A1: embedding gather + routing argmax (1 warp per token)
// =================================================================
__global__ void gather_route_kernel(const int* __restrict__ idx,
                                    const float* __restrict__ W_emb,
                                    const float* __restrict__ G) {
    const int tid  = threadIdx.x;
    const int warp = tid >> 5;
    const int lane = tid & 31;
    const int tok  = blockIdx.x * 8 + warp;
    const int id   = idx[tok];

    const float4* src = (const float4*)(W_emb + (size_t)id * Dm);
    const float4* g4  = (const float4*)G;
    float4* dst = (float4*)(g_x + (size_t)tok * Dm);

    float sc[NE] = {0.f, 0.f, 0.f, 0.f};
#pragma unroll
    for (int t = 0; t < 6; t++) {
        const int i = lane + t * 32;
        float4 v = src[i];
        dst[i] = v;
#pragma unroll
        for (int e = 0; e < NE; e++) {
            float4 gg = g4[e * (Dm / 4) + i];
            sc[e] += v.x * gg.x + v.y * gg.y + v.z * gg.z + v.w * gg.w;
        }
    }
#pragma unroll
    for (int off = 16; off > 0; off >>= 1)
#pragma unroll
        for (int e = 0; e < NE; e++)
            sc[e] += __shfl_down_sync(0xffffffffu, sc[e], off);
    if (lane == 0) {
        int best = 0;
        float bv = sc[0];
#pragma unroll
        for (int e = 1; e < NE; e++)
            if (sc[e] > bv) { bv = sc[e]; best = e; }
        g_win[tok] = best;
    }
}

// =================================================================
// Kernel A2: u = x @ W_in  (tiled SIMT GEMM, W_in staged in smem)
// =================================================================
__global__ void uproj_kernel(const float* __restrict__ W_in) {
    __shared__ float xs[16][64];
    __shared__ float ws[64][128];

    const int tid  = threadIdx.x;
    const int tok0 = blockIdx.x * 16;
    const int tx   = tid & 31;
    const int ty   = tid >> 5;
    const int j0   = tx * 4;
    const int t0   = ty * 2;

    float acc[2][4] = {};

#pragma unroll 1
    for (int ch = 0; ch < 12; ch++) {
        const int d0 = ch * 64;
        {
            const int row = tid >> 4, c4 = tid & 15;
            *(float4*)&xs[row][c4 * 4] =
                *(const float4*)(g_x + (size_t)(tok0 + row) * Dm + d0 + c4 * 4);
        }
        {
            const int d_loc = tid >> 2, e = tid & 3;
            const float4* srcw =
                (const float4*)(W_in + (size_t)e * Dm * Rr + (size_t)(d0 + d_loc) * Rr);
#pragma unroll
            for (int k = 0; k < 8; k++)
                *(float4*)&ws[d_loc][e * 32 + k * 4] = srcw[k];
        }
        __syncthreads();
#pragma unroll 8
        for (int d = 0; d < 64; d++) {
            const float4 w4 = *(const float4*)&ws[d][j0];
            const float x0 = xs[t0][d];
            const float x1 = xs[t0 + 1][d];
            acc[0][0] += x0 * w4.x; acc[0][1] += x0 * w4.y;
            acc[0][2] += x0 * w4.z; acc[0][3] += x0 * w4.w;
            acc[1][0] += x1 * w4.x; acc[1][1] += x1 * w4.y;
            acc[1][2] += x1 * w4.z; acc[1][3] += x1 * w4.w;
        }
        __syncthreads();
    }
#pragma unroll
    for (int tt = 0; tt < 2; tt++)
        *(float4*)&g_u[(size_t)(tok0 + t0 + tt) * (NE * Rr) + j0] =
            make_float4(acc[tt][0], acc[tt][1], acc[tt][2], acc[tt][3]);
}

// =================================================================
// Kernel B: recurrence, 16 blocks x 1 warp (one (e,b) chain per SM)
// =================================================================
__global__ void __launch_bounds__(32)
recur_kernel(const float* __restrict__ W_rec) {
    __shared__ int list_s[Tt];
    const int lane = threadIdx.x;
    const int e = blockIdx.x >> 2;
    const int b = blockIdx.x & 3;

    int n = 0;
    for (int base = 0; base < Tt; base += 32) {
        unsigned m = __ballot_sync(0xffffffffu, g_win[b * Tt + base + lane] == e);
        while (m) {
            int i = __ffs(m) - 1;
            m &= m - 1;
            list_s[n++] = base + i;
        }
    }

    float wcol[Rr];
#pragma unroll
    for (int s = 0; s < Rr; s++) wcol[s] = W_rec[(e * Rr + s) * Rr + lane];

    float st = 0.f;
    float unext = 0.f;
    if (n > 0) unext = g_u[(b * Tt + list_s[0]) * (NE * Rr) + e * Rr + lane];
    for (int i = 0; i < n; i++) {
        const float ucur = unext;
        if (i + 1 < n)
            unext = g_u[(b * Tt + list_s[i + 1]) * (NE * Rr) + e * Rr + lane];
        float a0 = ucur, a1 = 0.f, a2 = 0.f, a3 = 0.f;
#pragma unroll
        for (int s = 0; s < Rr; s += 4) {
            a0 += __shfl_sync(0xffffffffu, st, s)     * wcol[s];
            a1 += __shfl_sync(0xffffffffu, st, s + 1) * wcol[s + 1];
            a2 += __shfl_sync(0xffffffffu, st, s + 2) * wcol[s + 2];
            a3 += __shfl_sync(0xffffffffu, st, s + 3) * wcol[s + 3];
        }
        st = fast_tanh((a0 + a1) + (a2 + a3));
        g_cand[(b * Tt + list_s[i]) * Rr + lane] = st;
    }
}

// =================================================================
// Fused kernel C+W: blocks 0..2047  -> out_ln (y, LN, pack into g_hp)
//                   blocks 2048..   -> W_emb permute, coalesced stores
// out_ln is bandwidth-light and parallel; perm is the DRAM hog.
// Safe co-residency (no serial chain involved).
// =================================================================
__global__ void __launch_bounds__(256)
outln_perm_kernel(const float* __restrict__ W_out,
                  const float* __restrict__ gamma,
                  const float* __restrict__ beta,
                  const float* __restrict__ W) {
    const int tid = threadIdx.x;

    if (blockIdx.x < NTOK) {
        // ----------------- out_ln path -----------------
        __shared__ float cs[Rr];
        __shared__ float red[2][256];

        const int tok = blockIdx.x;
        const int e   = g_win[tok];

        if (tid < Rr) cs[tid] = g_cand[tok * Rr + tid];
        __syncthreads();

        float y[3];
        float s = 0.f, sq = 0.f;
#pragma unroll
        for (int i = 0; i < 3; i++) {
            const int d = tid + i * 256;
            float acc = g_x[tok * Dm + d];
            const float* wo = W_out + (size_t)e * Rr * Dm + d;
#pragma unroll
            for (int r = 0; r < Rr; r++) acc += cs[r] * wo[(size_t)r * Dm];
            y[i] = acc;
            s += acc;
            sq += acc * acc;
        }
        red[0][tid] = s;
        red[1][tid] = sq;
        __syncthreads();
        for (int off = 128; off > 0; off >>= 1) {
            if (tid < off) {
                red[0][tid] += red[0][tid + off];
                red[1][tid] += red[1][tid + off];
            }
            __syncthreads();
        }
        const float mean = red[0][0] * (1.f / Dm);
        const float var  = red[1][0] * (1.f / Dm) - mean * mean;
        const float rstd = rsqrtf(var + 1e-5f);

        const int mblk    = tok >> 7;
        const int r       = tok & 127;
        const int m16     = r >> 4;
        const int g       = r & 7;
        const int rowhalf = (r >> 3) & 1;
#pragma unroll
        for (int i = 0; i < 3; i++) {
            const int d = tid + i * 256;
            const __half hv = __float2half_rn((y[i] - mean) * rstd * gamma[d] + beta[d]);
            const int c = d >> 6, kk = d & 63;
            const int k16 = kk >> 4, kin = kk & 15;
            const int khalf = kin >> 3, kp = kin & 7;
            const int t4 = kp >> 1, par = kp & 1;
            __half* base = (__half*)(g_hp +
                ((size_t)(mblk * NCHUNK + c) * 4 + k16) * 256 + m16 * 32 + g * 4 + t4);
            base[(khalf * 2 + rowhalf) * 2 + par] = hv;
        }
        return;
    }

    // ----------------- perm path: coalesced uint4 stores -----------------
    // block = (nblk, c); thread = (k16, colpair): composes full uint4s.
    const int pb   = blockIdx.x - NTOK;
    const int nblk = pb / NCHUNK;
    const int c    = pb % NCHUNK;

    const int k16 = tid >> 6;        // 0..3
    const int cp  = tid & 63;        // colpair id
    const int wn  = cp >> 4;         // 0..3
    const int pr  = (cp >> 3) & 1;   // 0..1
    const int g   = cp & 7;          // 0..7
    const int colA = wn * 32 + pr * 16 + g;      // h=0 column
    const int gcolA = nblk * BN + colA;
    const int gcolB = gcolA + 8;                 // h=1 column

    __half hA[16], hB[16];
    {
        const float4* sa = (const float4*)(W + (size_t)gcolA * Dm + c * 64 + k16 * 16);
        if (gcolA < NV) {
#pragma unroll
            for (int i = 0; i < 4; i++) {
                float4 q = sa[i];
                hA[i * 4]     = __float2half_rn(q.x);
                hA[i * 4 + 1] = __float2half_rn(q.y);
                hA[i * 4 + 2] = __float2half_rn(q.z);
                hA[i * 4 + 3] = __float2half_rn(q.w);
            }
        } else {
#pragma unroll
            for (int i = 0; i < 16; i++) hA[i] = __float2half_rn(0.f);
        }
        const float4* sb = (const float4*)(W + (size_t)gcolB * Dm + c * 64 + k16 * 16);
        if (gcolB < NV) {
#pragma unroll
            for (int i = 0; i < 4; i++) {
                float4 q = sb[i];
                hB[i * 4]     = __float2half_rn(q.x);
                hB[i * 4 + 1] = __float2half_rn(q.y);
                hB[i * 4 + 2] = __float2half_rn(q.z);
                hB[i * 4 + 3] = __float2half_rn(q.w);
            }
        } else {
#pragma unroll
            for (int i = 0; i < 16; i++) hB[i] = __float2half_rn(0.f);
        }
    }

    uint4* dst = g_Wp + ((size_t)nblk * NCHUNK + c) * 1024 +
                 ((k16 * 4 + wn) * 2 + pr) * 32 + g * 4;
#pragma unroll
    for (int t4 = 0; t4 < 4; t4++) {
        uint4 U;
        U.x = h2u(hA[t4 * 2],     hA[t4 * 2 + 1]);
        U.y = h2u(hA[8 + t4 * 2], hA[8 + t4 * 2 + 1]);
        U.z = h2u(hB[t4 * 2],     hB[t4 * 2 + 1]);
        U.w = h2u(hB[8 + t4 * 2], hB[8 + t4 * 2 + 1]);
        dst[t4] = U;
    }
}

// =================================================================
// Kernel D (round-7 form, measured 492us): logits = h @ W_emb^T
// CTA 128x128, 8 warps (2 wm x 4 wn), warp tile 64x32.
// A+B smem, 3-stage ring (96KB) -> 2 CTAs/SM.
// =================================================================
constexpr int STAGE_BYTES = 32768;            // 16KB A + 16KB B
constexpr int SM_TOT      = 3 * STAGE_BYTES;  // 96KB

__global__ void __launch_bounds__(256, 2)
gemm_tc_kernel(float* __restrict__ out) {
    extern __shared__ char smem[];
    const uint32_t sbase = smem_u32(smem);
    const int tid  = threadIdx.x;
    const int warp = tid >> 5;
    const int lane = tid & 31;
    const int wm   = warp & 1;
    const int wn   = warp >> 1;   // 0..3
    const int g    = lane >> 2;
    const int t4   = lane & 3;
    const int mblk = blockIdx.x;
    const int nblk = blockIdx.y;

    const uint4* gA = g_hp + (size_t)mblk * NCHUNK * 1024;
    const uint4* gB = g_Wp + (size_t)nblk * NCHUNK * 1024;

    auto load_stage = [&](int slot, int c) {
        const uint32_t sS = sbase + slot * STAGE_BYTES;
        const uint4* a = gA + c * 1024;
        const uint4* b = gB + c * 1024;
#pragma unroll
        for (int t = 0; t < 4; t++) cp16(sS + (tid + t * 256) * 16, a + tid + t * 256);
#pragma unroll
        for (int t = 0; t < 4; t++) cp16(sS + 16384 + (tid + t * 256) * 16, b + tid + t * 256);
        CP_COMMIT();
    };

    load_stage(0, 0);
    load_stage(1, 1);

    float acc[4][4][4];
#pragma unroll
    for (int mt = 0; mt < 4; mt++)
#pragma unroll
        for (int nt = 0; nt < 4; nt++)
#pragma unroll
            for (int k = 0; k < 4; k++) acc[mt][nt][k] = 0.f;

    const uint32_t aoff = (wm * 4) * 512 + lane * 16;            // + k16*4096 + mt*512
    const uint32_t boff = 16384 + wn * 1024 + lane * 16;         // + k16*4096 + pr*512

#pragma unroll 1
    for (int c = 0; c < NCHUNK; c++) {
        if (c < NCHUNK - 1) { CP_WAIT(1); } else { CP_WAIT(0); }
        __syncthreads();
        if (c + 2 < NCHUNK) load_stage((c + 2) % 3, c + 2);

        const uint32_t sS = sbase + (c % 3) * STAGE_BYTES;
#pragma unroll
        for (int k16 = 0; k16 < 4; k16++) {
            uint32_t af[16], bf[8];
#pragma unroll
            for (int mt = 0; mt < 4; mt++)
                LDS128(af[mt * 4], af[mt * 4 + 1], af[mt * 4 + 2], af[mt * 4 + 3],
                       sS + aoff + k16 * 4096 + mt * 512);
#pragma unroll
            for (int pr = 0; pr < 2; pr++)
                LDS128(bf[pr * 4], bf[pr * 4 + 1], bf[pr * 4 + 2], bf[pr * 4 + 3],
                       sS + boff + k16 * 4096 + pr * 512);
#pragma unroll
            for (int mt = 0; mt < 4; mt++)
#pragma unroll
                for (int nt = 0; nt < 4; nt++) {
                    const int bi = (nt >> 1) * 4 + (nt & 1) * 2;
                    asm volatile(
                        "mma.sync.aligned.m16n8k16.row.col.f32.f16.f16.f32 "
                        "{%0,%1,%2,%3}, {%4,%5,%6,%7}, {%8,%9}, {%0,%1,%2,%3};\n"
                        : "+f"(acc[mt][nt][0]), "+f"(acc[mt][nt][1]),
                          "+f"(acc[mt][nt][2]), "+f"(acc[mt][nt][3])
                        : "r"(af[mt * 4]), "r"(af[mt * 4 + 1]),
                          "r"(af[mt * 4 + 2]), "r"(af[mt * 4 + 3]),
                          "r"(bf[bi]), "r"(bf[bi + 1]));
                }
        }
    }

    const int m0 = mblk * BM;
    const int n0 = nblk * BN;
#pragma unroll
    for (int mt = 0; mt < 4; mt++) {
        const int row0 = m0 + wm * 64 + mt * 16 + g;
#pragma unroll
        for (int nt = 0; nt < 4; nt++) {
            const int col = n0 + wn * 32 + nt * 8 + t4 * 2;
            if (col + 1 < NV) {
                out[(size_t)row0 * NV + col]           = acc[mt][nt][0];
                out[(size_t)row0 * NV + col + 1]       = acc[mt][nt][1];
                out[(size_t)(row0 + 8) * NV + col]     = acc[mt][nt][2];
                out[(size_t)(row0 + 8) * NV + col + 1] = acc[mt][nt][3];
            } else if (col < NV) {
                out[(size_t)row0 * NV + col]       = acc[mt][nt][0];
                out[(size_t)(row0 + 8) * NV + col] = acc[mt][nt][2];
            }
        }
    }
}

// =================================================================
// launch
// =================================================================
extern "C" void kernel_launch(void* const* d_in, const int* in_sizes, int n_in,
                              void* d_out, int out_size) {
    const int*   idx   = (const int*)d_in[0];
    const float* W_emb = (const float*)d_in[1];
    const float* G     = (const float*)d_in[2];
    const float* W_in  = (const float*)d_in[3];
    const float* W_rec = (const float*)d_in[4];
    const float* W_out = (const float*)d_in[5];
    const float* gamma = (const float*)d_in[6];
    const float* beta  = (const float*)d_in[7];
    float* out = (float*)d_out;

    cudaFuncSetAttribute(gemm_tc_kernel,
                         cudaFuncAttributeMaxDynamicSharedMemorySize, SM_TOT);

    gather_route_kernel<<<NTOK / 8, 256>>>(idx, W_emb, G);
    uproj_kernel<<<128, 256>>>(W_in);
    recur_kernel<<<16, 32>>>(W_rec);                    // runs alone: latency-critical
    outln_perm_kernel<<<NTOK + NCHUNK * NBLK, 256>>>(W_out, gamma, beta, W_emb);

    dim3 grid(MBLK, NBLK);
    gemm_tc_kernel<<<grid, 256, SM_TOT>>>(out);
}